// round 8
// baseline (speedup 1.0000x reference)
#include <cuda_runtime.h>
#include <cuda_fp16.h>
#include <math.h>

// Cone-beam forward projection, dual-layout fp16 packed volume.
//
// Layout A: g_volA[z][y][x], cell = 8 halves (b0,b1) x (z0,z1) x (x0,x1).
// Layout B: g_volB[z][x][y], cell = 8 halves (b0,b1) x (z0,z1) x (y0,y1).
// fp_kernel picks the layout whose fast axis matches the warp's lane-varying
// world axis, so every angle gets lane-contiguous 16B-cell gathers.
// Interp: x-lerp and y-lerp in half2 (batch pair in lanes), z-lerp + acc fp32.
// Prep: single smem-tiled pass builds BOTH layouts with coalesced I/O.
// vol in: [B=2, Z=96, Y=96, X=96] fp32. out: [B=2, A=48, V=96, U=96] fp32.

#define NZ 96
#define NY 96
#define NX 96
#define NV 96
#define NU 96
#define NA 48
#define NS 96

#define DSO 500.0f
#define DSD 1000.0f
#define DDET 2.0f

#define STEP 1.7320508075688772f
#define T0   416.86156123669393f

#define VOL_N (NZ * NY * NX)     // 884736
#define SROW 96
#define SZ (NX * NY)             // 9216

__device__ uint4 g_volA[VOL_N];  // 14.2 MB
__device__ uint4 g_volB[VOL_N];  // 14.2 MB

static __device__ __forceinline__ unsigned h2u(__half2 h) {
    union { __half2 h; unsigned u; } cvt; cvt.h = h; return cvt.u;
}
static __device__ __forceinline__ __half2 u2h(unsigned u) {
    union { unsigned u; __half2 h; } cvt; cvt.u = u; return cvt.h;
}

// ---------------------------------------------------------------------------
// Tiled prep: block handles a 32x32 (y,x) tile at one z. Stages clamped
// 33x33 neighborhoods of (b0,b1) half2 for planes z and z+1 in smem, then
// writes both layouts coalesced.  grid = (3,3,96), block = 256.
// ---------------------------------------------------------------------------
__global__ void __launch_bounds__(256) prep_tiled(const float* __restrict__ vol) {
    __shared__ unsigned s0[33][34];   // plane z   : (b0,b1) packed; pad to 34
    __shared__ unsigned s1[33][34];   // plane z+1

    int x0t = blockIdx.x * 32;
    int y0t = blockIdx.y * 32;
    int z   = blockIdx.z;
    int zp  = min(z + 1, NZ - 1);

    const float* b0 = vol;
    const float* b1 = vol + VOL_N;

    int tid = threadIdx.x;   // 0..255

    for (int k = tid; k < 33 * 33; k += 256) {
        int yl = k / 33;
        int xl = k - yl * 33;
        int gy = min(y0t + yl, NY - 1);
        int gx = min(x0t + xl, NX - 1);
        int i  = z * SZ + gy * NX + gx;
        int ip = zp * SZ + gy * NX + gx;
        s0[yl][xl] = h2u(__floats2half2_rn(b0[i],  b1[i]));
        s1[yl][xl] = h2u(__floats2half2_rn(b0[ip], b1[ip]));
    }
    __syncthreads();

    int tx = tid & 31;
    int ty = tid >> 5;

    // layout A: g_volA[z][y][x], cell = (z0x0, z0x1, z1x0, z1x1); x fast
    for (int yr = ty; yr < 32; yr += 8) {
        uint4 q;
        q.x = s0[yr][tx];
        q.y = s0[yr][tx + 1];
        q.z = s1[yr][tx];
        q.w = s1[yr][tx + 1];
        g_volA[z * SZ + (y0t + yr) * NX + (x0t + tx)] = q;
    }

    // layout B: g_volB[z][x][y], cell = (z0y0, z0y1, z1y0, z1y1); y fast
    for (int xr = ty; xr < 32; xr += 8) {
        uint4 q;
        q.x = s0[tx][xr];
        q.y = s0[tx + 1][xr];
        q.z = s1[tx][xr];
        q.w = s1[tx + 1][xr];
        g_volB[z * SZ + (x0t + xr) * NY + (y0t + tx)] = q;
    }
}

__global__ void __launch_bounds__(256) fp_kernel(float* __restrict__ out) {
    int idx = blockIdx.x * blockDim.x + threadIdx.x;
    // 48 * 96 * 96 = 442368 threads; each serves both batches
    int u = idx % NU;
    int v = (idx / NU) % NV;
    int a = idx / (NU * NV);

    float theta = (float)a * (6.2831853071795864769f / (float)NA);
    float s = sinf(theta);
    float c = cosf(theta);

    float srcx = DSO * c;
    float srcy = DSO * s;

    float uu = ((float)u - (NU - 1) * 0.5f) * DDET;
    float vv = ((float)v - (NV - 1) * 0.5f) * DDET;

    float px = -(DSD - DSO) * c - uu * s;
    float py = -(DSD - DSO) * s + uu * c;
    float pz = vv;

    float dx = px - srcx;
    float dy = py - srcy;
    float dz = pz;
    float inv = rsqrtf(fmaf(dx, dx, fmaf(dy, dy, dz * dz)));
    dx *= inv; dy *= inv; dz *= inv;

    // ray/box slab test, box = [-47.5, 47.5]^3 world (symmetric in x/y)
    const float H = 47.5f;
    float ix_ = 1.0f / dx, iy_ = 1.0f / dy, iz_ = 1.0f / dz;
    float tx1 = (-H - srcx) * ix_, tx2 = (H - srcx) * ix_;
    float ty1 = (-H - srcy) * iy_, ty2 = (H - srcy) * iy_;
    float tz1 = (-H) * iz_,        tz2 = (H) * iz_;
    float tmin = fmaxf(fmaxf(fminf(tx1, tx2), fminf(ty1, ty2)), fminf(tz1, tz2));
    float tmax = fminf(fminf(fmaxf(tx1, tx2), fmaxf(ty1, ty2)), fmaxf(tz1, tz2));

    int i0 = 0, i1 = 0;
    if (tmax > tmin) {
        i0 = max(0, (int)floorf((tmin - T0) / STEP - 0.5f) - 1);
        i1 = min(NS, (int)ceilf((tmax - T0) / STEP - 0.5f) + 2);
    }

    // pick layout so the warp's lane-varying axis is the fast (packed) axis
    bool useA = fabsf(s) >= fabsf(c);
    const uint4* __restrict__ g = useA ? g_volA : g_volB;

    float fdx = useA ? dx : dy;
    float fdy = useA ? dy : dx;
    float cx = (useA ? srcx : srcy) + 47.5f;
    float cy = (useA ? srcy : srcx) + 47.5f;
    float cz = 47.5f;

    float acc0 = 0.0f, acc1 = 0.0f;

    #pragma unroll 4
    for (int i = i0; i < i1; i++) {
        float t = fmaf((float)i + 0.5f, STEP, T0);
        float x = fmaf(fdx, t, cx);   // fast axis
        float y = fmaf(fdy, t, cy);   // slow axis
        float z = fmaf(dz, t, cz);

        // compact validity: min/max reduction
        float mn = fminf(fminf(x, y), z);
        float mx = fmaxf(fmaxf(x, y), z);
        if ((mn >= 0.0f) & (mx <= 95.0f)) {
            int x0 = min((int)x, NX - 2);
            int y0 = min((int)y, NY - 2);
            int z0 = min((int)z, NZ - 2);
            float fx = x - (float)x0;
            float fy = y - (float)y0;
            float fz = z - (float)z0;

            const uint4* p = g + (z0 * SZ + y0 * SROW + x0);
            uint4 r0 = __ldg(p);          // slow row 0: (z0f0, z0f1, z1f0, z1f1)
            uint4 r1 = __ldg(p + SROW);   // slow row 1

            __half2 fx2 = __float2half2_rn(fx);
            __half2 fy2 = __float2half2_rn(fy);

            // x-lerp (4 independent pairs), batch pair rides in half2 lanes
            __half2 q00 = u2h(r0.x), q01 = u2h(r0.y);  // y0: z0x0, z0x1
            __half2 q02 = u2h(r0.z), q03 = u2h(r0.w);  // y0: z1x0, z1x1
            __half2 q10 = u2h(r1.x), q11 = u2h(r1.y);  // y1: z0x0, z0x1
            __half2 q12 = u2h(r1.z), q13 = u2h(r1.w);  // y1: z1x0, z1x1

            __half2 xz0y0 = __hfma2(fx2, __hsub2(q01, q00), q00);
            __half2 xz1y0 = __hfma2(fx2, __hsub2(q03, q02), q02);
            __half2 xz0y1 = __hfma2(fx2, __hsub2(q11, q10), q10);
            __half2 xz1y1 = __hfma2(fx2, __hsub2(q13, q12), q12);

            // y-lerp (2 independent pairs)
            __half2 yz0 = __hfma2(fy2, __hsub2(xz0y1, xz0y0), xz0y0);
            __half2 yz1 = __hfma2(fy2, __hsub2(xz1y1, xz1y0), xz1y0);

            // convert survivors, z-lerp + accumulate in fp32
            float2 f0 = __half22float2(yz0);
            float2 f1 = __half22float2(yz1);
            acc0 += fmaf(fz, f1.x - f0.x, f0.x);
            acc1 += fmaf(fz, f1.y - f0.y, f0.y);
        }
    }

    out[idx] = acc0 * STEP;
    out[idx + NA * NV * NU] = acc1 * STEP;
}

extern "C" void kernel_launch(void* const* d_in, const int* in_sizes, int n_in,
                              void* d_out, int out_size) {
    const float* vol = (const float*)d_in[0];
    float* out = (float*)d_out;

    {
        dim3 grid(NX / 32, NY / 32, NZ);   // (3,3,96)
        prep_tiled<<<grid, 256>>>(vol);
    }
    {
        int total = NA * NV * NU;   // 442368
        int threads = 256;
        int blocks = (total + threads - 1) / threads;
        fp_kernel<<<blocks, threads>>>(out);
    }
}

// round 9
// speedup vs baseline: 1.1091x; 1.1091x over previous
#include <cuda_runtime.h>
#include <cuda_fp16.h>
#include <math.h>

// Cone-beam forward projection, dual-layout fp16 packed volume.
//
// Layout A: g_volA[z][y][x], cell = 8 halves (b0,b1) x (z0,z1) x (x0,x1).
// Layout B: g_volB[z][x][y], cell = 8 halves (b0,b1) x (z0,z1) x (y0,y1).
// fp_kernel picks the layout whose fast axis matches the warp's lane-varying
// world axis, so every angle gets lane-contiguous 16B-cell gathers.
// Wave-tail fix: each ray is split into TWO half-rays (gridDim.y = 2),
// partial sums combined with atomicAdd into a zeroed output.
// vol in: [B=2, Z=96, Y=96, X=96] fp32. out: [B=2, A=48, V=96, U=96] fp32.

#define NZ 96
#define NY 96
#define NX 96
#define NV 96
#define NU 96
#define NA 48
#define NS 96

#define DSO 500.0f
#define DSD 1000.0f
#define DDET 2.0f

#define STEP 1.7320508075688772f
#define T0   416.86156123669393f

#define VOL_N (NZ * NY * NX)     // 884736
#define SROW 96
#define SZ (NX * NY)             // 9216
#define NRAY (NA * NV * NU)      // 442368

__device__ uint4 g_volA[VOL_N];  // 14.2 MB
__device__ uint4 g_volB[VOL_N];  // 14.2 MB

static __device__ __forceinline__ unsigned h2u(__half2 h) {
    union { __half2 h; unsigned u; } cvt; cvt.h = h; return cvt.u;
}
static __device__ __forceinline__ __half2 u2h(unsigned u) {
    union { unsigned u; __half2 h; } cvt; cvt.u = u; return cvt.h;
}

// ---------------------------------------------------------------------------
// Tiled prep: block handles a 32x32 (y,x) tile at one z. Stages clamped
// 33x33 neighborhoods of (b0,b1) half2 for planes z and z+1 in smem, then
// writes both layouts coalesced.  grid = (3,3,96), block = 256.
// ---------------------------------------------------------------------------
__global__ void __launch_bounds__(256) prep_tiled(const float* __restrict__ vol) {
    __shared__ unsigned s0[33][34];
    __shared__ unsigned s1[33][34];

    int x0t = blockIdx.x * 32;
    int y0t = blockIdx.y * 32;
    int z   = blockIdx.z;
    int zp  = min(z + 1, NZ - 1);

    const float* b0 = vol;
    const float* b1 = vol + VOL_N;

    int tid = threadIdx.x;

    for (int k = tid; k < 33 * 33; k += 256) {
        int yl = k / 33;
        int xl = k - yl * 33;
        int gy = min(y0t + yl, NY - 1);
        int gx = min(x0t + xl, NX - 1);
        int i  = z * SZ + gy * NX + gx;
        int ip = zp * SZ + gy * NX + gx;
        s0[yl][xl] = h2u(__floats2half2_rn(b0[i],  b1[i]));
        s1[yl][xl] = h2u(__floats2half2_rn(b0[ip], b1[ip]));
    }
    __syncthreads();

    int tx = tid & 31;
    int ty = tid >> 5;

    for (int yr = ty; yr < 32; yr += 8) {
        uint4 q;
        q.x = s0[yr][tx];
        q.y = s0[yr][tx + 1];
        q.z = s1[yr][tx];
        q.w = s1[yr][tx + 1];
        g_volA[z * SZ + (y0t + yr) * NX + (x0t + tx)] = q;
    }

    for (int xr = ty; xr < 32; xr += 8) {
        uint4 q;
        q.x = s0[tx][xr];
        q.y = s0[tx + 1][xr];
        q.z = s1[tx][xr];
        q.w = s1[tx + 1][xr];
        g_volB[z * SZ + (x0t + xr) * NY + (y0t + tx)] = q;
    }
}

__global__ void __launch_bounds__(256) zero_kernel(float4* __restrict__ out) {
    int i = blockIdx.x * blockDim.x + threadIdx.x;
    if (i < (2 * NRAY) / 4) out[i] = make_float4(0.f, 0.f, 0.f, 0.f);
}

__global__ void __launch_bounds__(256) fp_kernel(float* __restrict__ out) {
    int idx = blockIdx.x * blockDim.x + threadIdx.x;   // ray id, 0..NRAY-1
    int half = blockIdx.y;                             // 0 or 1
    int u = idx % NU;
    int v = (idx / NU) % NV;
    int a = idx / (NU * NV);

    float theta = (float)a * (6.2831853071795864769f / (float)NA);
    float s = sinf(theta);
    float c = cosf(theta);

    float srcx = DSO * c;
    float srcy = DSO * s;

    float uu = ((float)u - (NU - 1) * 0.5f) * DDET;
    float vv = ((float)v - (NV - 1) * 0.5f) * DDET;

    float px = -(DSD - DSO) * c - uu * s;
    float py = -(DSD - DSO) * s + uu * c;
    float pz = vv;

    float dx = px - srcx;
    float dy = py - srcy;
    float dz = pz;
    float inv = rsqrtf(fmaf(dx, dx, fmaf(dy, dy, dz * dz)));
    dx *= inv; dy *= inv; dz *= inv;

    // ray/box slab test, box = [-47.5, 47.5]^3 world
    const float H = 47.5f;
    float ix_ = 1.0f / dx, iy_ = 1.0f / dy, iz_ = 1.0f / dz;
    float tx1 = (-H - srcx) * ix_, tx2 = (H - srcx) * ix_;
    float ty1 = (-H - srcy) * iy_, ty2 = (H - srcy) * iy_;
    float tz1 = (-H) * iz_,        tz2 = (H) * iz_;
    float tmin = fmaxf(fmaxf(fminf(tx1, tx2), fminf(ty1, ty2)), fminf(tz1, tz2));
    float tmax = fminf(fminf(fmaxf(tx1, tx2), fmaxf(ty1, ty2)), fmaxf(tz1, tz2));

    int i0 = 0, i1 = 0;
    if (tmax > tmin) {
        i0 = max(0, (int)floorf((tmin - T0) / STEP - 0.5f) - 1);
        i1 = min(NS, (int)ceilf((tmax - T0) / STEP - 0.5f) + 2);
    }

    // split the sample range between the two half-ray threads
    int mid = (i0 + i1) >> 1;
    int sBeg = half ? mid : i0;
    int sEnd = half ? i1 : mid;

    bool useA = fabsf(s) >= fabsf(c);
    const uint4* __restrict__ g = useA ? g_volA : g_volB;

    float fdx = useA ? dx : dy;
    float fdy = useA ? dy : dx;
    float cx = (useA ? srcx : srcy) + 47.5f;
    float cy = (useA ? srcy : srcx) + 47.5f;
    float cz = 47.5f;

    float acc0 = 0.0f, acc1 = 0.0f;

    #pragma unroll 4
    for (int i = sBeg; i < sEnd; i++) {
        float t = fmaf((float)i + 0.5f, STEP, T0);
        float x = fmaf(fdx, t, cx);   // fast axis
        float y = fmaf(fdy, t, cy);   // slow axis
        float z = fmaf(dz, t, cz);

        float mn = fminf(fminf(x, y), z);
        float mx = fmaxf(fmaxf(x, y), z);
        if ((mn >= 0.0f) & (mx <= 95.0f)) {
            int x0 = min((int)x, NX - 2);
            int y0 = min((int)y, NY - 2);
            int z0 = min((int)z, NZ - 2);
            float fx = x - (float)x0;
            float fy = y - (float)y0;
            float fz = z - (float)z0;

            const uint4* p = g + (z0 * SZ + y0 * SROW + x0);
            uint4 r0 = __ldg(p);          // slow row 0: (z0f0, z0f1, z1f0, z1f1)
            uint4 r1 = __ldg(p + SROW);   // slow row 1

            float wd = fx * fy;
            float wb = fx - wd;
            float wc = fy - wd;
            float wa = 1.0f - fx - wc;

            float2 a0 = __half22float2(u2h(r0.x));
            float2 a1 = __half22float2(u2h(r0.y));
            float2 a2 = __half22float2(u2h(r0.z));
            float2 a3 = __half22float2(u2h(r0.w));
            float2 c0_ = __half22float2(u2h(r1.x));
            float2 c1_ = __half22float2(u2h(r1.y));
            float2 c2_ = __half22float2(u2h(r1.z));
            float2 c3_ = __half22float2(u2h(r1.w));

            float p0x = fmaf(a0.x, wa, fmaf(a1.x, wb, fmaf(c0_.x, wc, c1_.x * wd)));
            float p0y = fmaf(a0.y, wa, fmaf(a1.y, wb, fmaf(c0_.y, wc, c1_.y * wd)));
            float p1x = fmaf(a2.x, wa, fmaf(a3.x, wb, fmaf(c2_.x, wc, c3_.x * wd)));
            float p1y = fmaf(a2.y, wa, fmaf(a3.y, wb, fmaf(c2_.y, wc, c3_.y * wd)));

            acc0 += fmaf(fz, p1x - p0x, p0x);
            acc1 += fmaf(fz, p1y - p0y, p0y);
        }
    }

    // combine the two half-rays (exactly 2 adds per address -> deterministic)
    atomicAdd(&out[idx],        acc0 * STEP);
    atomicAdd(&out[idx + NRAY], acc1 * STEP);
}

extern "C" void kernel_launch(void* const* d_in, const int* in_sizes, int n_in,
                              void* d_out, int out_size) {
    const float* vol = (const float*)d_in[0];
    float* out = (float*)d_out;

    {
        dim3 grid(NX / 32, NY / 32, NZ);   // (3,3,96)
        prep_tiled<<<grid, 256>>>(vol);
    }
    {
        int n4 = (2 * NRAY) / 4;           // 221184
        zero_kernel<<<(n4 + 255) / 256, 256>>>((float4*)out);
    }
    {
        dim3 grid(NRAY / 256, 2);          // (1728, 2) -> 884736 threads
        fp_kernel<<<grid, 256>>>(out);
    }
}

// round 10
// speedup vs baseline: 1.1118x; 1.0024x over previous
#include <cuda_runtime.h>
#include <cuda_fp16.h>
#include <math.h>

// Cone-beam forward projection, dual-layout fp16 packed volume.
//
// Layout A: g_volA[z][y][x], cell = 8 halves (b0,b1) x (z0,z1) x (x0,x1).
// Layout B: g_volB[z][x][y], cell = 8 halves (b0,b1) x (z0,z1) x (y0,y1).
// fp_kernel picks the layout whose fast axis matches the warp's lane-varying
// world axis, so every angle gets lane-contiguous 16B-cell gathers.
// Each ray is split into TWO half-rays (gridDim.y = 2); partials combined
// with atomicAdd into a zeroed output (2 adds/address -> deterministic).
// Prep: 2-z-slab smem-tiled pass builds BOTH layouts, conflict-free.
// vol in: [B=2, Z=96, Y=96, X=96] fp32. out: [B=2, A=48, V=96, U=96] fp32.

#define NZ 96
#define NY 96
#define NX 96
#define NV 96
#define NU 96
#define NA 48
#define NS 96

#define DSO 500.0f
#define DSD 1000.0f
#define DDET 2.0f

#define STEP 1.7320508075688772f
#define T0   416.86156123669393f

#define VOL_N (NZ * NY * NX)     // 884736
#define SROW 96
#define SZ (NX * NY)             // 9216
#define NRAY (NA * NV * NU)      // 442368

__device__ uint4 g_volA[VOL_N];  // 14.2 MB
__device__ uint4 g_volB[VOL_N];  // 14.2 MB

static __device__ __forceinline__ unsigned h2u(__half2 h) {
    union { __half2 h; unsigned u; } cvt; cvt.h = h; return cvt.u;
}
static __device__ __forceinline__ __half2 u2h(unsigned u) {
    union { unsigned u; __half2 h; } cvt; cvt.u = u; return cvt.h;
}

// ---------------------------------------------------------------------------
// Tiled prep: block = 32x32 (y,x) tile x 2 z-outputs. Stages 3 clamped
// 33x33 planes of (b0,b1) half2 in smem (rows padded to 35 words ->
// transpose reads conflict-free), then writes both layouts coalesced.
// grid = (3,3,48), block = 256.
// ---------------------------------------------------------------------------
__global__ void __launch_bounds__(256) prep_tiled(const float* __restrict__ vol) {
    __shared__ unsigned s[3][33][35];

    int x0t = blockIdx.x * 32;
    int y0t = blockIdx.y * 32;
    int zb  = blockIdx.z * 2;
    int z2  = min(zb + 2, NZ - 1);

    const float* b0 = vol;
    const float* b1 = vol + VOL_N;

    int tid = threadIdx.x;

    for (int k = tid; k < 33 * 33; k += 256) {
        int yl = k / 33;
        int xl = k - yl * 33;
        int gy = min(y0t + yl, NY - 1);
        int gx = min(x0t + xl, NX - 1);
        int base = gy * NX + gx;
        int i0 = zb * SZ + base;
        int i1 = (zb + 1) * SZ + base;
        int i2 = z2 * SZ + base;
        s[0][yl][xl] = h2u(__floats2half2_rn(b0[i0], b1[i0]));
        s[1][yl][xl] = h2u(__floats2half2_rn(b0[i1], b1[i1]));
        s[2][yl][xl] = h2u(__floats2half2_rn(b0[i2], b1[i2]));
    }
    __syncthreads();

    int tx = tid & 31;
    int ty = tid >> 5;

    #pragma unroll
    for (int dz = 0; dz < 2; dz++) {
        int z = zb + dz;

        // layout A: g_volA[z][y][x], cell = (z0x0, z0x1, z1x0, z1x1); x fast
        for (int yr = ty; yr < 32; yr += 8) {
            uint4 q;
            q.x = s[dz][yr][tx];
            q.y = s[dz][yr][tx + 1];
            q.z = s[dz + 1][yr][tx];
            q.w = s[dz + 1][yr][tx + 1];
            g_volA[z * SZ + (y0t + yr) * NX + (x0t + tx)] = q;
        }

        // layout B: g_volB[z][x][y], cell = (z0y0, z0y1, z1y0, z1y1); y fast
        for (int xr = ty; xr < 32; xr += 8) {
            uint4 q;
            q.x = s[dz][tx][xr];
            q.y = s[dz][tx + 1][xr];
            q.z = s[dz + 1][tx][xr];
            q.w = s[dz + 1][tx + 1][xr];
            g_volB[z * SZ + (x0t + xr) * NY + (y0t + tx)] = q;
        }
    }
}

__global__ void __launch_bounds__(256) zero_kernel(float4* __restrict__ out) {
    int i = blockIdx.x * blockDim.x + threadIdx.x;
    if (i < (2 * NRAY) / 4) out[i] = make_float4(0.f, 0.f, 0.f, 0.f);
}

__global__ void __launch_bounds__(256) fp_kernel(float* __restrict__ out) {
    int idx = blockIdx.x * blockDim.x + threadIdx.x;   // ray id, 0..NRAY-1
    int half = blockIdx.y;                             // 0 or 1
    int u = idx % NU;
    int v = (idx / NU) % NV;
    int a = idx / (NU * NV);

    float theta = (float)a * (6.2831853071795864769f / (float)NA);
    float s = sinf(theta);
    float c = cosf(theta);

    float srcx = DSO * c;
    float srcy = DSO * s;

    float uu = ((float)u - (NU - 1) * 0.5f) * DDET;
    float vv = ((float)v - (NV - 1) * 0.5f) * DDET;

    float px = -(DSD - DSO) * c - uu * s;
    float py = -(DSD - DSO) * s + uu * c;
    float pz = vv;

    float dx = px - srcx;
    float dy = py - srcy;
    float dz = pz;
    float inv = rsqrtf(fmaf(dx, dx, fmaf(dy, dy, dz * dz)));
    dx *= inv; dy *= inv; dz *= inv;

    // ray/box slab test, box = [-47.5, 47.5]^3 world
    const float H = 47.5f;
    float ix_ = 1.0f / dx, iy_ = 1.0f / dy, iz_ = 1.0f / dz;
    float tx1 = (-H - srcx) * ix_, tx2 = (H - srcx) * ix_;
    float ty1 = (-H - srcy) * iy_, ty2 = (H - srcy) * iy_;
    float tz1 = (-H) * iz_,        tz2 = (H) * iz_;
    float tmin = fmaxf(fmaxf(fminf(tx1, tx2), fminf(ty1, ty2)), fminf(tz1, tz2));
    float tmax = fminf(fminf(fmaxf(tx1, tx2), fmaxf(ty1, ty2)), fmaxf(tz1, tz2));

    int i0 = 0, i1 = 0;
    if (tmax > tmin) {
        i0 = max(0, (int)floorf((tmin - T0) / STEP - 0.5f) - 1);
        i1 = min(NS, (int)ceilf((tmax - T0) / STEP - 0.5f) + 2);
    }

    // split the sample range between the two half-ray threads
    int mid = (i0 + i1) >> 1;
    int sBeg = half ? mid : i0;
    int sEnd = half ? i1 : mid;

    bool useA = fabsf(s) >= fabsf(c);
    const uint4* __restrict__ g = useA ? g_volA : g_volB;

    float fdx = useA ? dx : dy;
    float fdy = useA ? dy : dx;
    float cx = (useA ? srcx : srcy) + 47.5f;
    float cy = (useA ? srcy : srcx) + 47.5f;
    float cz = 47.5f;

    float acc0 = 0.0f, acc1 = 0.0f;

    #pragma unroll 4
    for (int i = sBeg; i < sEnd; i++) {
        float t = fmaf((float)i + 0.5f, STEP, T0);
        float x = fmaf(fdx, t, cx);   // fast axis
        float y = fmaf(fdy, t, cy);   // slow axis
        float z = fmaf(dz, t, cz);

        float mn = fminf(fminf(x, y), z);
        float mx = fmaxf(fmaxf(x, y), z);
        if ((mn >= 0.0f) & (mx <= 95.0f)) {
            int x0 = min((int)x, NX - 2);
            int y0 = min((int)y, NY - 2);
            int z0 = min((int)z, NZ - 2);
            float fx = x - (float)x0;
            float fy = y - (float)y0;
            float fz = z - (float)z0;

            const uint4* p = g + (z0 * SZ + y0 * SROW + x0);
            uint4 r0 = __ldg(p);          // slow row 0: (z0f0, z0f1, z1f0, z1f1)
            uint4 r1 = __ldg(p + SROW);   // slow row 1

            float wd = fx * fy;
            float wb = fx - wd;
            float wc = fy - wd;
            float wa = 1.0f - fx - wc;

            float2 a0 = __half22float2(u2h(r0.x));
            float2 a1 = __half22float2(u2h(r0.y));
            float2 a2 = __half22float2(u2h(r0.z));
            float2 a3 = __half22float2(u2h(r0.w));
            float2 c0_ = __half22float2(u2h(r1.x));
            float2 c1_ = __half22float2(u2h(r1.y));
            float2 c2_ = __half22float2(u2h(r1.z));
            float2 c3_ = __half22float2(u2h(r1.w));

            float p0x = fmaf(a0.x, wa, fmaf(a1.x, wb, fmaf(c0_.x, wc, c1_.x * wd)));
            float p0y = fmaf(a0.y, wa, fmaf(a1.y, wb, fmaf(c0_.y, wc, c1_.y * wd)));
            float p1x = fmaf(a2.x, wa, fmaf(a3.x, wb, fmaf(c2_.x, wc, c3_.x * wd)));
            float p1y = fmaf(a2.y, wa, fmaf(a3.y, wb, fmaf(c2_.y, wc, c3_.y * wd)));

            acc0 += fmaf(fz, p1x - p0x, p0x);
            acc1 += fmaf(fz, p1y - p0y, p0y);
        }
    }

    // combine the two half-rays (exactly 2 adds per address -> deterministic)
    atomicAdd(&out[idx],        acc0 * STEP);
    atomicAdd(&out[idx + NRAY], acc1 * STEP);
}

extern "C" void kernel_launch(void* const* d_in, const int* in_sizes, int n_in,
                              void* d_out, int out_size) {
    const float* vol = (const float*)d_in[0];
    float* out = (float*)d_out;

    {
        int n4 = (2 * NRAY) / 4;           // 221184
        zero_kernel<<<(n4 + 255) / 256, 256>>>((float4*)out);
    }
    {
        dim3 grid(NX / 32, NY / 32, NZ / 2);   // (3,3,48)
        prep_tiled<<<grid, 256>>>(vol);
    }
    {
        dim3 grid(NRAY / 256, 2);          // (1728, 2) -> 884736 threads
        fp_kernel<<<grid, 256>>>(out);
    }
}

// round 11
// speedup vs baseline: 1.1286x; 1.0152x over previous
#include <cuda_runtime.h>
#include <cuda_fp16.h>
#include <math.h>

// Cone-beam forward projection, dual-layout fp16 packed volume.
//
// Layout A: g_volA[z][y][x], cell = 8 halves (b0,b1) x (z0,z1) x (x0,x1).
// Layout B: g_volB[z][x][y], cell = 8 halves (b0,b1) x (z0,z1) x (y0,y1).
// fp_kernel picks the layout whose fast axis matches the warp's lane-varying
// world axis, so every angle gets lane-contiguous 16B-cell gathers.
// Each ray is split into TWO half-rays (gridDim.y = 2); partials combined
// with atomicAdd into a zeroed output (2 adds/address -> deterministic).
// Prep: 2-z-slab smem-tiled pass builds BOTH layouts AND zeroes the output
// (prep runs before fp in-stream, so ordering is guaranteed).
// vol in: [B=2, Z=96, Y=96, X=96] fp32. out: [B=2, A=48, V=96, U=96] fp32.

#define NZ 96
#define NY 96
#define NX 96
#define NV 96
#define NU 96
#define NA 48
#define NS 96

#define DSO 500.0f
#define DSD 1000.0f
#define DDET 2.0f

#define STEP 1.7320508075688772f
#define T0   416.86156123669393f

#define VOL_N (NZ * NY * NX)     // 884736
#define SROW 96
#define SZ (NX * NY)             // 9216
#define NRAY (NA * NV * NU)      // 442368
#define OUT4 ((2 * NRAY) / 4)    // 221184 float4s
#define NPREPBLK (3 * 3 * 48)    // 432
#define ZPB ((OUT4 + NPREPBLK - 1) / NPREPBLK)   // 512 float4 per prep block

__device__ uint4 g_volA[VOL_N];  // 14.2 MB
__device__ uint4 g_volB[VOL_N];  // 14.2 MB

static __device__ __forceinline__ unsigned h2u(__half2 h) {
    union { __half2 h; unsigned u; } cvt; cvt.h = h; return cvt.u;
}
static __device__ __forceinline__ __half2 u2h(unsigned u) {
    union { unsigned u; __half2 h; } cvt; cvt.u = u; return cvt.h;
}

// ---------------------------------------------------------------------------
// Tiled prep: block = 32x32 (y,x) tile x 2 z-outputs. Stages 3 clamped
// 33x33 planes of (b0,b1) half2 in smem (rows padded to 35 words ->
// transpose reads conflict-free), then writes both layouts coalesced.
// Also zeroes a 512-float4 chunk of the output buffer.
// grid = (3,3,48), block = 256.
// ---------------------------------------------------------------------------
__global__ void __launch_bounds__(256) prep_tiled(const float* __restrict__ vol,
                                                  float4* __restrict__ outz) {
    __shared__ unsigned s[3][33][35];

    int x0t = blockIdx.x * 32;
    int y0t = blockIdx.y * 32;
    int zb  = blockIdx.z * 2;
    int z2  = min(zb + 2, NZ - 1);

    // zero my chunk of the output (independent of the staging below)
    {
        int blk = (blockIdx.z * gridDim.y + blockIdx.y) * gridDim.x + blockIdx.x;
        int base = blk * ZPB + threadIdx.x;
        const float4 z4 = make_float4(0.f, 0.f, 0.f, 0.f);
        #pragma unroll
        for (int r = 0; r < ZPB / 256; r++) {
            int j = base + r * 256;
            if (j < OUT4) outz[j] = z4;
        }
    }

    const float* b0 = vol;
    const float* b1 = vol + VOL_N;

    int tid = threadIdx.x;

    // incremental row walk over 33x33 (avoids div/mod per element)
    {
        int yl = tid / 33;          // one div at entry
        int xl = tid - yl * 33;
        for (int k = tid; k < 33 * 33; k += 256) {
            int gy = min(y0t + yl, NY - 1);
            int gx = min(x0t + xl, NX - 1);
            int base = gy * NX + gx;
            int i0 = zb * SZ + base;
            int i1 = (zb + 1) * SZ + base;
            int i2 = z2 * SZ + base;
            s[0][yl][xl] = h2u(__floats2half2_rn(b0[i0], b1[i0]));
            s[1][yl][xl] = h2u(__floats2half2_rn(b0[i1], b1[i1]));
            s[2][yl][xl] = h2u(__floats2half2_rn(b0[i2], b1[i2]));
            // advance by 256 = 7*33 + 25
            yl += 7; xl += 25;
            if (xl >= 33) { xl -= 33; yl += 1; }
        }
    }
    __syncthreads();

    int tx = tid & 31;
    int ty = tid >> 5;

    #pragma unroll
    for (int dz = 0; dz < 2; dz++) {
        int z = zb + dz;

        // layout A: g_volA[z][y][x], cell = (z0x0, z0x1, z1x0, z1x1); x fast
        for (int yr = ty; yr < 32; yr += 8) {
            uint4 q;
            q.x = s[dz][yr][tx];
            q.y = s[dz][yr][tx + 1];
            q.z = s[dz + 1][yr][tx];
            q.w = s[dz + 1][yr][tx + 1];
            g_volA[z * SZ + (y0t + yr) * NX + (x0t + tx)] = q;
        }

        // layout B: g_volB[z][x][y], cell = (z0y0, z0y1, z1y0, z1y1); y fast
        for (int xr = ty; xr < 32; xr += 8) {
            uint4 q;
            q.x = s[dz][tx][xr];
            q.y = s[dz][tx + 1][xr];
            q.z = s[dz + 1][tx][xr];
            q.w = s[dz + 1][tx + 1][xr];
            g_volB[z * SZ + (x0t + xr) * NY + (y0t + tx)] = q;
        }
    }
}

__global__ void __launch_bounds__(256) fp_kernel(float* __restrict__ out) {
    int idx = blockIdx.x * blockDim.x + threadIdx.x;   // ray id, 0..NRAY-1
    int half = blockIdx.y;                             // 0 or 1
    int u = idx % NU;
    int v = (idx / NU) % NV;
    int a = idx / (NU * NV);

    float theta = (float)a * (6.2831853071795864769f / (float)NA);
    float s = sinf(theta);
    float c = cosf(theta);

    float srcx = DSO * c;
    float srcy = DSO * s;

    float uu = ((float)u - (NU - 1) * 0.5f) * DDET;
    float vv = ((float)v - (NV - 1) * 0.5f) * DDET;

    float px = -(DSD - DSO) * c - uu * s;
    float py = -(DSD - DSO) * s + uu * c;
    float pz = vv;

    float dx = px - srcx;
    float dy = py - srcy;
    float dz = pz;
    float inv = rsqrtf(fmaf(dx, dx, fmaf(dy, dy, dz * dz)));
    dx *= inv; dy *= inv; dz *= inv;

    // ray/box slab test, box = [-47.5, 47.5]^3 world
    const float H = 47.5f;
    float ix_ = 1.0f / dx, iy_ = 1.0f / dy, iz_ = 1.0f / dz;
    float tx1 = (-H - srcx) * ix_, tx2 = (H - srcx) * ix_;
    float ty1 = (-H - srcy) * iy_, ty2 = (H - srcy) * iy_;
    float tz1 = (-H) * iz_,        tz2 = (H) * iz_;
    float tmin = fmaxf(fmaxf(fminf(tx1, tx2), fminf(ty1, ty2)), fminf(tz1, tz2));
    float tmax = fminf(fminf(fmaxf(tx1, tx2), fmaxf(ty1, ty2)), fmaxf(tz1, tz2));

    int i0 = 0, i1 = 0;
    if (tmax > tmin) {
        i0 = max(0, (int)floorf((tmin - T0) / STEP - 0.5f) - 1);
        i1 = min(NS, (int)ceilf((tmax - T0) / STEP - 0.5f) + 2);
    }

    // split the sample range between the two half-ray threads
    int mid = (i0 + i1) >> 1;
    int sBeg = half ? mid : i0;
    int sEnd = half ? i1 : mid;

    bool useA = fabsf(s) >= fabsf(c);
    const uint4* __restrict__ g = useA ? g_volA : g_volB;

    float fdx = useA ? dx : dy;
    float fdy = useA ? dy : dx;
    float cx = (useA ? srcx : srcy) + 47.5f;
    float cy = (useA ? srcy : srcx) + 47.5f;
    float cz = 47.5f;

    float acc0 = 0.0f, acc1 = 0.0f;

    #pragma unroll 4
    for (int i = sBeg; i < sEnd; i++) {
        float t = fmaf((float)i + 0.5f, STEP, T0);
        float x = fmaf(fdx, t, cx);   // fast axis
        float y = fmaf(fdy, t, cy);   // slow axis
        float z = fmaf(dz, t, cz);

        float mn = fminf(fminf(x, y), z);
        float mx = fmaxf(fmaxf(x, y), z);
        if ((mn >= 0.0f) & (mx <= 95.0f)) {
            int x0 = min((int)x, NX - 2);
            int y0 = min((int)y, NY - 2);
            int z0 = min((int)z, NZ - 2);
            float fx = x - (float)x0;
            float fy = y - (float)y0;
            float fz = z - (float)z0;

            const uint4* p = g + (z0 * SZ + y0 * SROW + x0);
            uint4 r0 = __ldg(p);          // slow row 0: (z0f0, z0f1, z1f0, z1f1)
            uint4 r1 = __ldg(p + SROW);   // slow row 1

            float wd = fx * fy;
            float wb = fx - wd;
            float wc = fy - wd;
            float wa = 1.0f - fx - wc;

            float2 a0 = __half22float2(u2h(r0.x));
            float2 a1 = __half22float2(u2h(r0.y));
            float2 a2 = __half22float2(u2h(r0.z));
            float2 a3 = __half22float2(u2h(r0.w));
            float2 c0_ = __half22float2(u2h(r1.x));
            float2 c1_ = __half22float2(u2h(r1.y));
            float2 c2_ = __half22float2(u2h(r1.z));
            float2 c3_ = __half22float2(u2h(r1.w));

            float p0x = fmaf(a0.x, wa, fmaf(a1.x, wb, fmaf(c0_.x, wc, c1_.x * wd)));
            float p0y = fmaf(a0.y, wa, fmaf(a1.y, wb, fmaf(c0_.y, wc, c1_.y * wd)));
            float p1x = fmaf(a2.x, wa, fmaf(a3.x, wb, fmaf(c2_.x, wc, c3_.x * wd)));
            float p1y = fmaf(a2.y, wa, fmaf(a3.y, wb, fmaf(c2_.y, wc, c3_.y * wd)));

            acc0 += fmaf(fz, p1x - p0x, p0x);
            acc1 += fmaf(fz, p1y - p0y, p0y);
        }
    }

    // combine the two half-rays (exactly 2 adds per address -> deterministic)
    atomicAdd(&out[idx],        acc0 * STEP);
    atomicAdd(&out[idx + NRAY], acc1 * STEP);
}

extern "C" void kernel_launch(void* const* d_in, const int* in_sizes, int n_in,
                              void* d_out, int out_size) {
    const float* vol = (const float*)d_in[0];
    float* out = (float*)d_out;

    {
        dim3 grid(NX / 32, NY / 32, NZ / 2);   // (3,3,48) = 432 blocks
        prep_tiled<<<grid, 256>>>(vol, (float4*)out);
    }
    {
        dim3 grid(NRAY / 256, 2);          // (1728, 2) -> 884736 threads
        fp_kernel<<<grid, 256>>>(out);
    }
}

// round 12
// speedup vs baseline: 1.1572x; 1.0253x over previous
#include <cuda_runtime.h>
#include <cuda_fp16.h>
#include <math.h>

// Cone-beam forward projection, dual-layout fp16 packed volume.
//
// Layout A: g_volA[z][y][x], cell = 8 halves (b0,b1) x (z0,z1) x (x0,x1).
// Layout B: g_volB[z][x][y], cell = 8 halves (b0,b1) x (z0,z1) x (y0,y1).
// fp_kernel picks the layout whose fast axis matches the warp's lane-varying
// world axis -> lane-contiguous 16B-cell gathers at every angle.
// Interp: x-lerp in half2 (batch pair in lanes), y/z-lerp + masked acc in
// packed f32x2 (FFMA2). Each ray split into two half-rays (gridDim.y=2),
// partials combined via atomicAdd (exactly 2 adds/address -> deterministic).
// Prep: 2-z-slab smem-tiled pass builds BOTH layouts and zeroes the output.
// vol in: [B=2, Z=96, Y=96, X=96] fp32. out: [B=2, A=48, V=96, U=96] fp32.

#define NZ 96
#define NY 96
#define NX 96
#define NV 96
#define NU 96
#define NA 48
#define NS 96

#define DSO 500.0f
#define DSD 1000.0f
#define DDET 2.0f

#define STEP 1.7320508075688772f
#define T0   416.86156123669393f

#define VOL_N (NZ * NY * NX)     // 884736
#define SROW 96
#define SZ (NX * NY)             // 9216
#define NRAY (NA * NV * NU)      // 442368
#define OUT4 ((2 * NRAY) / 4)    // 221184 float4s
#define NPREPBLK (3 * 3 * 48)    // 432
#define ZPB ((OUT4 + NPREPBLK - 1) / NPREPBLK)   // 512 float4 per prep block

__device__ uint4 g_volA[VOL_N];  // 14.2 MB
__device__ uint4 g_volB[VOL_N];  // 14.2 MB

typedef unsigned long long u64;

static __device__ __forceinline__ unsigned h2u(__half2 h) {
    union { __half2 h; unsigned u; } cvt; cvt.h = h; return cvt.u;
}
static __device__ __forceinline__ __half2 u2h(unsigned u) {
    union { unsigned u; __half2 h; } cvt; cvt.u = u; return cvt.h;
}
static __device__ __forceinline__ u64 pk2(float lo, float hi) {
    u64 r;
    asm("mov.b64 %0, {%1, %2};" : "=l"(r) : "f"(lo), "f"(hi));
    return r;
}
static __device__ __forceinline__ u64 fma2_(u64 a, u64 b, u64 c) {
    u64 d;
    asm("fma.rn.f32x2 %0, %1, %2, %3;" : "=l"(d) : "l"(a), "l"(b), "l"(c));
    return d;
}
// lerp(a,b,f) over packed pairs: a + f*(b-a) computed as fma(f,b, fma(-f,a,a))
static __device__ __forceinline__ u64 lerp2(u64 a, u64 b, u64 f2, u64 nf2) {
    return fma2_(f2, b, fma2_(nf2, a, a));
}

// ---------------------------------------------------------------------------
// Tiled prep: block = 32x32 (y,x) tile x 2 z-outputs. Stages 3 clamped
// 33x33 planes of (b0,b1) half2 in smem (rows padded to 35 words ->
// transpose reads conflict-free), writes both layouts coalesced, and also
// zeroes a 512-float4 chunk of the output. grid = (3,3,48), block = 256.
// ---------------------------------------------------------------------------
__global__ void __launch_bounds__(256) prep_tiled(const float* __restrict__ vol,
                                                  float4* __restrict__ outz) {
    __shared__ unsigned s[3][33][35];

    int x0t = blockIdx.x * 32;
    int y0t = blockIdx.y * 32;
    int zb  = blockIdx.z * 2;
    int z2  = min(zb + 2, NZ - 1);

    // zero my chunk of the output
    {
        int blk = (blockIdx.z * gridDim.y + blockIdx.y) * gridDim.x + blockIdx.x;
        int base = blk * ZPB + threadIdx.x;
        const float4 z4 = make_float4(0.f, 0.f, 0.f, 0.f);
        #pragma unroll
        for (int r = 0; r < ZPB / 256; r++) {
            int j = base + r * 256;
            if (j < OUT4) outz[j] = z4;
        }
    }

    const float* b0 = vol;
    const float* b1 = vol + VOL_N;

    int tid = threadIdx.x;

    // incremental row walk over 33x33
    {
        int yl = tid / 33;
        int xl = tid - yl * 33;
        for (int k = tid; k < 33 * 33; k += 256) {
            int gy = min(y0t + yl, NY - 1);
            int gx = min(x0t + xl, NX - 1);
            int base = gy * NX + gx;
            int i0 = zb * SZ + base;
            int i1 = (zb + 1) * SZ + base;
            int i2 = z2 * SZ + base;
            s[0][yl][xl] = h2u(__floats2half2_rn(b0[i0], b1[i0]));
            s[1][yl][xl] = h2u(__floats2half2_rn(b0[i1], b1[i1]));
            s[2][yl][xl] = h2u(__floats2half2_rn(b0[i2], b1[i2]));
            yl += 7; xl += 25;
            if (xl >= 33) { xl -= 33; yl += 1; }
        }
    }
    __syncthreads();

    int tx = tid & 31;
    int ty = tid >> 5;

    #pragma unroll
    for (int dz = 0; dz < 2; dz++) {
        int z = zb + dz;

        for (int yr = ty; yr < 32; yr += 8) {
            uint4 q;
            q.x = s[dz][yr][tx];
            q.y = s[dz][yr][tx + 1];
            q.z = s[dz + 1][yr][tx];
            q.w = s[dz + 1][yr][tx + 1];
            g_volA[z * SZ + (y0t + yr) * NX + (x0t + tx)] = q;
        }

        for (int xr = ty; xr < 32; xr += 8) {
            uint4 q;
            q.x = s[dz][tx][xr];
            q.y = s[dz][tx + 1][xr];
            q.z = s[dz + 1][tx][xr];
            q.w = s[dz + 1][tx + 1][xr];
            g_volB[z * SZ + (x0t + xr) * NY + (y0t + tx)] = q;
        }
    }
}

__global__ void __launch_bounds__(256) fp_kernel(float* __restrict__ out) {
    int idx = blockIdx.x * blockDim.x + threadIdx.x;   // ray id
    int half = blockIdx.y;                             // 0 or 1
    int u = idx % NU;
    int v = (idx / NU) % NV;
    int a = idx / (NU * NV);

    float theta = (float)a * (6.2831853071795864769f / (float)NA);
    float s = sinf(theta);
    float c = cosf(theta);

    float srcx = DSO * c;
    float srcy = DSO * s;

    float uu = ((float)u - (NU - 1) * 0.5f) * DDET;
    float vv = ((float)v - (NV - 1) * 0.5f) * DDET;

    float px = -(DSD - DSO) * c - uu * s;
    float py = -(DSD - DSO) * s + uu * c;
    float pz = vv;

    float dx = px - srcx;
    float dy = py - srcy;
    float dz = pz;
    float inv = rsqrtf(fmaf(dx, dx, fmaf(dy, dy, dz * dz)));
    dx *= inv; dy *= inv; dz *= inv;

    // ray/box slab test, box = [-47.5, 47.5]^3 world
    const float H = 47.5f;
    float ix_ = 1.0f / dx, iy_ = 1.0f / dy, iz_ = 1.0f / dz;
    float tx1 = (-H - srcx) * ix_, tx2 = (H - srcx) * ix_;
    float ty1 = (-H - srcy) * iy_, ty2 = (H - srcy) * iy_;
    float tz1 = (-H) * iz_,        tz2 = (H) * iz_;
    float tmin = fmaxf(fmaxf(fminf(tx1, tx2), fminf(ty1, ty2)), fminf(tz1, tz2));
    float tmax = fminf(fminf(fmaxf(tx1, tx2), fmaxf(ty1, ty2)), fmaxf(tz1, tz2));

    int i0 = 0, i1 = 0;
    if (tmax > tmin) {
        i0 = max(0, (int)floorf((tmin - T0) / STEP - 0.5f) - 1);
        i1 = min(NS, (int)ceilf((tmax - T0) / STEP - 0.5f) + 2);
    }

    int mid = (i0 + i1) >> 1;
    int sBeg = half ? mid : i0;
    int sEnd = half ? i1 : mid;

    bool useA = fabsf(s) >= fabsf(c);
    const uint4* __restrict__ g = useA ? g_volA : g_volB;

    float fdx = useA ? dx : dy;
    float fdy = useA ? dy : dx;
    float cx = (useA ? srcx : srcy) + 47.5f;
    float cy = (useA ? srcy : srcx) + 47.5f;
    float cz = 47.5f;

    u64 acc = pk2(0.0f, 0.0f);   // (batch0, batch1)

    #pragma unroll 4
    for (int i = sBeg; i < sEnd; i++) {
        float t = fmaf((float)i + 0.5f, STEP, T0);
        float x = fmaf(fdx, t, cx);   // fast axis
        float y = fmaf(fdy, t, cy);   // slow axis
        float z = fmaf(dz, t, cz);

        float mn = fminf(fminf(x, y), z);
        float mx = fmaxf(fmaxf(x, y), z);
        if ((mn >= 0.0f) & (mx <= 95.0f)) {
            int x0 = min((int)x, NX - 2);
            int y0 = min((int)y, NY - 2);
            int z0 = min((int)z, NZ - 2);
            float fx = x - (float)x0;
            float fy = y - (float)y0;
            float fz = z - (float)z0;

            const uint4* p = g + (z0 * SZ + y0 * SROW + x0);
            uint4 r0 = __ldg(p);          // slow row 0: (z0f0, z0f1, z1f0, z1f1)
            uint4 r1 = __ldg(p + SROW);   // slow row 1

            // ---- x-lerp in half2 (batch pair in lanes), 4 independent ----
            __half2 fx2 = __float2half2_rn(fx);
            __half2 q00 = u2h(r0.x), q01 = u2h(r0.y);  // y0: z0
            __half2 q02 = u2h(r0.z), q03 = u2h(r0.w);  // y0: z1
            __half2 q10 = u2h(r1.x), q11 = u2h(r1.y);  // y1: z0
            __half2 q12 = u2h(r1.z), q13 = u2h(r1.w);  // y1: z1

            __half2 xz0y0 = __hfma2(fx2, __hsub2(q01, q00), q00);
            __half2 xz1y0 = __hfma2(fx2, __hsub2(q03, q02), q02);
            __half2 xz0y1 = __hfma2(fx2, __hsub2(q11, q10), q10);
            __half2 xz1y1 = __hfma2(fx2, __hsub2(q13, q12), q12);

            // ---- convert 4 survivors, pack into f32x2 pairs ----
            float2 f00 = __half22float2(xz0y0);
            float2 f10 = __half22float2(xz1y0);
            float2 f01 = __half22float2(xz0y1);
            float2 f11 = __half22float2(xz1y1);
            u64 P0y0 = pk2(f00.x, f00.y);
            u64 P1y0 = pk2(f10.x, f10.y);
            u64 P0y1 = pk2(f01.x, f01.y);
            u64 P1y1 = pk2(f11.x, f11.y);

            // ---- y-lerp, z-lerp, masked accumulate in f32x2 ----
            u64 fy2  = pk2(fy,  fy);
            u64 nfy2 = pk2(-fy, -fy);
            u64 fz2  = pk2(fz,  fz);
            u64 nfz2 = pk2(-fz, -fz);

            u64 z0p = lerp2(P0y0, P0y1, fy2, nfy2);
            u64 z1p = lerp2(P1y0, P1y1, fy2, nfy2);
            u64 r   = lerp2(z0p, z1p, fz2, nfz2);

            u64 one2 = pk2(1.0f, 1.0f);
            acc = fma2_(r, one2, acc);
        }
    }

    float acc0, acc1;
    asm("mov.b64 {%0, %1}, %2;" : "=f"(acc0), "=f"(acc1) : "l"(acc));

    atomicAdd(&out[idx],        acc0 * STEP);
    atomicAdd(&out[idx + NRAY], acc1 * STEP);
}

extern "C" void kernel_launch(void* const* d_in, const int* in_sizes, int n_in,
                              void* d_out, int out_size) {
    const float* vol = (const float*)d_in[0];
    float* out = (float*)d_out;

    {
        dim3 grid(NX / 32, NY / 32, NZ / 2);   // (3,3,48)
        prep_tiled<<<grid, 256>>>(vol, (float4*)out);
    }
    {
        dim3 grid(NRAY / 256, 2);          // (1728, 2)
        fp_kernel<<<grid, 256>>>(out);
    }
}